// round 9
// baseline (speedup 1.0000x reference)
#include <cuda_runtime.h>
#include <cuda_bf16.h>
#include <math.h>
#include <stdint.h>

#define DIMV 768
#define NLV 12
#define DSV 16
#define DIV 1536
#define TOKV 8192      // 32 batches * 256 tokens
#define LV 256
#define GSV 5
#define KANK (DIMV * GSV)   // 3840

// ---------------- scratch (static device globals; no allocation allowed) ----
__device__ float g_tmp[TOKV * DIMV];                 // im2col / KAN accumulator
__device__ float g_h[TOKV * DIMV];                   // running hidden state (exact)
__device__ float g_hr[TOKV * DIMV];                  // tf32-rounded copy of h
__device__ float g_xr[(size_t)TOKV * 2 * DIV];       // in_proj output (x1|res)
__device__ float g_x1[(size_t)TOKV * DIV];           // post conv+silu
__device__ float g_yg[(size_t)TOKV * DIV];           // gated y (tf32-rounded)
__device__ float g_Ad[TOKV * DSV];
__device__ float g_Bd[TOKV * DSV];
__device__ float g_ys[TOKV * DSV];
__device__ float g_basis[(size_t)TOKV * KANK];       // KAN spline basis (rounded)
__device__ float g_wkan[(size_t)DIMV * KANK];        // repacked+rounded coeff
// tf32-rounded weight staging
__device__ float g_wi[(size_t)NLV * 2 * DIV * DIMV];
__device__ float g_wo[(size_t)NLV * DIMV * DIV];
__device__ float g_wp[DIMV * DIMV];
__device__ float g_wkb[4 * DIMV * DIMV];

// ---------------- PTX helpers ----------------------------------------------
__device__ __forceinline__ uint32_t smem_u32(const void* p) {
    uint32_t a;
    asm("{ .reg .u64 t; cvta.to.shared.u64 t, %1; cvt.u32.u64 %0, t; }"
        : "=r"(a) : "l"(p));
    return a;
}
__device__ __forceinline__ void ldsm4(uint32_t& r0, uint32_t& r1,
                                      uint32_t& r2, uint32_t& r3, uint32_t addr)
{
    asm volatile("ldmatrix.sync.aligned.m8n8.x4.shared.b16 {%0,%1,%2,%3}, [%4];"
                 : "=r"(r0), "=r"(r1), "=r"(r2), "=r"(r3) : "r"(addr));
}
__device__ __forceinline__ float tf32r(float v)
{
    uint32_t r;
    asm("cvt.rna.tf32.f32 %0, %1;" : "=r"(r) : "f"(v));
    return __uint_as_float(r);
}
__device__ __forceinline__ float4 tf32r4(float4 v)
{
    v.x = tf32r(v.x); v.y = tf32r(v.y); v.z = tf32r(v.z); v.w = tf32r(v.w);
    return v;
}
__device__ __forceinline__ void mma_tf32(float* c, const uint32_t* a, const uint32_t* b)
{
    asm volatile(
        "mma.sync.aligned.m16n8k8.row.col.f32.tf32.tf32.f32 "
        "{%0,%1,%2,%3}, {%4,%5,%6,%7}, {%8,%9}, {%0,%1,%2,%3};"
        : "+f"(c[0]), "+f"(c[1]), "+f"(c[2]), "+f"(c[3])
        : "r"(a[0]), "r"(a[1]), "r"(a[2]), "r"(a[3]), "r"(b[0]), "r"(b[1]));
}
__device__ __forceinline__ void cp16(uint32_t dst, const void* src)
{
    asm volatile("cp.async.cg.shared.global [%0], [%1], 16;"
                 :: "r"(dst), "l"(src) : "memory");
}
__device__ __forceinline__ void cp_commit()
{
    asm volatile("cp.async.commit_group;" ::: "memory");
}
template<int NN> __device__ __forceinline__ void cp_wait()
{
    asm volatile("cp.async.wait_group %0;" :: "n"(NN) : "memory");
}

// ---------------- tensor-core GEMM (TF32 mma.sync, 3-stage pipeline) --------
#define APITCH 144
#define TILE_B (128 * APITCH)        // 18432
#define STAGE_B (2 * TILE_B)         // 36864
#define NSTAGE 3
#define SMEMT (NSTAGE * STAGE_B)     // 110592

template<bool BIAS, bool ACC, bool RST>
__global__ __launch_bounds__(256, 2)
void tgemm(const float* __restrict__ A, const float* __restrict__ W,
           const float* __restrict__ bias, float* __restrict__ C,
           float* __restrict__ Cr, int M, int N, int K)
{
    extern __shared__ char smem[];
    const uint32_t sb0 = smem_u32(smem);
    const int tid = threadIdx.x, lane = tid & 31, wid = tid >> 5;
    const int row0 = blockIdx.y * 128, col0 = blockIdx.x * 128;
    const int rm = (wid >> 2) * 64, cn = (wid & 3) * 32;

    const float* gA = A + (size_t)row0 * K;
    const float* gW = W + (size_t)col0 * K;

    const int lrow = tid >> 3;          // 0..31
    const int lch  = tid & 7;           // 16B chunk 0..7

    auto issue = [&](int p, int s) {
        const int k0 = p * 32;
        const uint32_t dstb = sb0 + s * STAGE_B;
#pragma unroll
        for (int i = 0; i < 4; i++) {
            int row = lrow + i * 32;
            cp16(dstb + row * APITCH + lch * 16,
                 gA + (size_t)row * K + k0 + lch * 4);
        }
#pragma unroll
        for (int i = 0; i < 4; i++) {
            int row = lrow + i * 32;
            cp16(dstb + TILE_B + row * APITCH + lch * 16,
                 gW + (size_t)row * K + k0 + lch * 4);
        }
        cp_commit();
    };

    float acc[4][4][4];
#pragma unroll
    for (int a = 0; a < 4; a++)
#pragma unroll
        for (int b = 0; b < 4; b++)
#pragma unroll
            for (int q = 0; q < 4; q++) acc[a][b][q] = 0.f;

    const uint32_t aOff = (uint32_t)(rm + ((lane >> 3) & 1) * 8 + (lane & 7)) * APITCH
                        + (lane >> 4) * 16;
    const uint32_t wOff = (uint32_t)(cn + ((lane >> 4) & 1) * 8 + (lane & 7)) * APITCH
                        + ((lane >> 3) & 1) * 16;

    const int npan = K >> 5;
    issue(0, 0);
    if (npan > 1) issue(1, 1);

    int slot = 0;       // stage holding panel p
    int nslot = 2;      // stage to fill with panel p+2

    for (int p = 0; p < npan; p++) {
        if (p + 2 < npan) {
            issue(p + 2, nslot);
            cp_wait<2>();
        } else if (p + 1 < npan) {
            cp_wait<1>();
        } else {
            cp_wait<0>();
        }
        __syncthreads();

        const uint32_t sbase = sb0 + slot * STAGE_B;
#pragma unroll
        for (int ks = 0; ks < 4; ks++) {
            const uint32_t kb = ks * 32;
            uint32_t Af[4][4], Wf[4][2];
#pragma unroll
            for (int mt = 0; mt < 4; mt++)
                ldsm4(Af[mt][0], Af[mt][1], Af[mt][2], Af[mt][3],
                      sbase + aOff + mt * (16 * APITCH) + kb);
#pragma unroll
            for (int bt = 0; bt < 2; bt++) {
                uint32_t r0, r1, r2, r3;
                ldsm4(r0, r1, r2, r3,
                      sbase + TILE_B + wOff + bt * (16 * APITCH) + kb);
                Wf[bt * 2][0] = r0; Wf[bt * 2][1] = r1;
                Wf[bt * 2 + 1][0] = r2; Wf[bt * 2 + 1][1] = r3;
            }
#pragma unroll
            for (int mt = 0; mt < 4; mt++)
#pragma unroll
                for (int nt = 0; nt < 4; nt++)
                    mma_tf32(acc[mt][nt], Af[mt], Wf[nt]);
        }
        __syncthreads();

        slot = (slot == NSTAGE - 1) ? 0 : slot + 1;
        nslot = (nslot == NSTAGE - 1) ? 0 : nslot + 1;
    }

    // epilogue
#pragma unroll
    for (int mt = 0; mt < 4; mt++) {
#pragma unroll
        for (int nt = 0; nt < 4; nt++) {
            int r = row0 + rm + mt * 16 + (lane >> 2);
            int c = col0 + cn + nt * 8 + (lane & 3) * 2;
            float bx = 0.f, by = 0.f;
            if (BIAS) { bx = bias[c]; by = bias[c + 1]; }
#pragma unroll
            for (int half = 0; half < 2; half++) {
                size_t off = (size_t)(r + half * 8) * N + c;
                float vx = acc[mt][nt][half * 2 + 0] + bx;
                float vy = acc[mt][nt][half * 2 + 1] + by;
                if (ACC) { vx += C[off]; vy += C[off + 1]; }
                *reinterpret_cast<float2*>(C + off) = make_float2(vx, vy);
                if (RST)
                    *reinterpret_cast<float2*>(Cr + off) =
                        make_float2(tf32r(vx), tf32r(vy));
            }
        }
    }
}

// ---------------- elementwise / small kernels (float4-vectorized) ----------

__global__ void round4_k(const float* __restrict__ src, float* __restrict__ dst, int n4)
{
    int idx = blockIdx.x * blockDim.x + threadIdx.x;
    if (idx >= n4) return;
    reinterpret_cast<float4*>(dst)[idx] =
        tf32r4(reinterpret_cast<const float4*>(src)[idx]);
}

__global__ void im2col_k(const float* __restrict__ x)
{
    int idx = blockIdx.x * blockDim.x + threadIdx.x;    // over TOKV*DIMV/4
    if (idx >= TOKV * DIMV / 4) return;
    int col4 = (idx % (DIMV / 4)) * 4;
    int row  = idx / (DIMV / 4);
    int b = row >> 8, t = row & 255;
    int py = t >> 4, px = t & 15;
    int c = col4 >> 8, rj = col4 & 255;
    int r = rj >> 4, s = rj & 15;
    const float4 v = *reinterpret_cast<const float4*>(
        x + (((size_t)(b * 3 + c) * 256) + py * 16 + r) * 256 + px * 16 + s);
    reinterpret_cast<float4*>(g_tmp)[idx] = tf32r4(v);
}

__global__ void addpos_k(const float* __restrict__ pos)
{
    int idx = blockIdx.x * blockDim.x + threadIdx.x;    // over TOKV*DIMV/4
    if (idx >= TOKV * DIMV / 4) return;
    int d4  = idx % (DIMV / 4);
    int row = idx / (DIMV / 4);
    float4 h = reinterpret_cast<const float4*>(g_h)[idx];
    float4 p = reinterpret_cast<const float4*>(pos)[(row & 255) * (DIMV / 4) + d4];
    h.x += p.x; h.y += p.y; h.z += p.z; h.w += p.w;
    reinterpret_cast<float4*>(g_h)[idx] = h;
    reinterpret_cast<float4*>(g_hr)[idx] = tf32r4(h);
}

// depthwise causal conv (kernel 4) + silu, 4 channels / thread
__global__ void conv_silu_k(const float* __restrict__ cw, const float* __restrict__ cb)
{
    int idx = blockIdx.x * blockDim.x + threadIdx.x;    // over TOKV*DIV/4
    if (idx >= TOKV * DIV / 4) return;
    int c4  = (idx % (DIV / 4)) * 4;
    int row = idx / (DIV / 4);
    int l = row & 255;

    float4 a = *reinterpret_cast<const float4*>(cb + c4);
    float4 w0 = *reinterpret_cast<const float4*>(cw + (c4 + 0) * 4);
    float4 w1 = *reinterpret_cast<const float4*>(cw + (c4 + 1) * 4);
    float4 w2 = *reinterpret_cast<const float4*>(cw + (c4 + 2) * 4);
    float4 w3 = *reinterpret_cast<const float4*>(cw + (c4 + 3) * 4);
    const float* wk[4] = { (const float*)&w0, (const float*)&w1,
                           (const float*)&w2, (const float*)&w3 };
#pragma unroll
    for (int k = 0; k < 4; k++) {
        int l2 = l - 3 + k;
        if (l2 >= 0) {
            float4 xv = *reinterpret_cast<const float4*>(
                g_xr + (size_t)(row - 3 + k) * (2 * DIV) + c4);
            a.x = fmaf(xv.x, wk[0][k], a.x);
            a.y = fmaf(xv.y, wk[1][k], a.y);
            a.z = fmaf(xv.z, wk[2][k], a.z);
            a.w = fmaf(xv.w, wk[3][k], a.w);
        }
    }
    a.x = a.x / (1.f + expf(-a.x));
    a.y = a.y / (1.f + expf(-a.y));
    a.z = a.z / (1.f + expf(-a.z));
    a.w = a.w / (1.f + expf(-a.w));
    reinterpret_cast<float4*>(g_x1)[idx] = a;
}

// fused dt + Bp projection + softplus/Ad/Bd
__global__ __launch_bounds__(256)
void dtbp_k(const float* __restrict__ dtw, const float* __restrict__ dtb,
            const float* __restrict__ xpw, const float* __restrict__ alog)
{
    __shared__ float Xs[64][36];
    __shared__ float Ws2[32][33];

    const int tid = threadIdx.x;
    const int lane = tid & 31;
    const int wid = tid >> 5;
    const int row0 = blockIdx.x * 64;

    const int xrow = tid >> 3;
    const int xk4  = (tid & 7) * 4;

    float acc[8];
#pragma unroll
    for (int r = 0; r < 8; r++) acc[r] = 0.f;

    const float* wsrc = (xrow < 16)
        ? (dtw + (size_t)xrow * DIV)
        : (xpw + (size_t)xrow * DIV);

    for (int kt = 0; kt < DIV; kt += 32) {
        float4 xa = *(const float4*)(g_x1 + (size_t)(row0 + xrow) * DIV + kt + xk4);
        float4 xb = *(const float4*)(g_x1 + (size_t)(row0 + 32 + xrow) * DIV + kt + xk4);
        *(float4*)&Xs[xrow][xk4] = xa;
        *(float4*)&Xs[32 + xrow][xk4] = xb;
        float4 wv = *(const float4*)(wsrc + kt + xk4);
        Ws2[xrow][xk4 + 0] = wv.x; Ws2[xrow][xk4 + 1] = wv.y;
        Ws2[xrow][xk4 + 2] = wv.z; Ws2[xrow][xk4 + 3] = wv.w;
        __syncthreads();
#pragma unroll
        for (int kk = 0; kk < 32; kk++) {
            float w = Ws2[lane][kk];
#pragma unroll
            for (int r = 0; r < 8; r++)
                acc[r] = fmaf(Xs[wid * 8 + r][kk], w, acc[r]);
        }
        __syncthreads();
    }

    float dtb_v = (lane < DSV) ? dtb[lane] : 0.f;
    float negA  = (lane < DSV) ? -expf(alog[lane]) : 0.f;

#pragma unroll
    for (int r = 0; r < 8; r++) {
        int row = row0 + wid * 8 + r;
        const float* xr = g_x1 + (size_t)row * DIV;
        float s = xr[lane] + xr[lane + 32] + xr[lane + 64];
#pragma unroll
        for (int o = 16; o; o >>= 1) s += __shfl_xor_sync(0xffffffffu, s, o);
        float u = s * (1.f / 96.f);
        float bp = __shfl_sync(0xffffffffu, acc[r], (lane & 15) + 16);
        if (lane < DSV) {
            float raw = acc[r] + dtb_v;
            float dtv = fmaxf(raw, 0.f) + log1pf(expf(-fabsf(raw)));
            g_Ad[row * DSV + lane] = expf(negA * dtv);
            g_Bd[row * DSV + lane] = dtv * bp * u;
        }
    }
}

// warp-parallel linear-recurrence scan: one warp per (batch, state) pair.
__global__ void scan_k()   // <<<64, 256>>> : 512 warps
{
    int g = blockIdx.x * blockDim.x + threadIdx.x;
    int w = g >> 5, lane = g & 31;
    int b = w >> 4, n = w & 15;
    size_t idx0 = (size_t)b * LV * DSV + n + (size_t)(lane * 8) * DSV;

    float a[8], bb[8];
    float A = 1.f, B = 0.f;
#pragma unroll
    for (int i = 0; i < 8; i++) {
        a[i]  = g_Ad[idx0 + (size_t)i * DSV];
        bb[i] = g_Bd[idx0 + (size_t)i * DSV];
        B = B * a[i] + bb[i];
        A = A * a[i];
    }
    float Ai = A, Bi = B;
#pragma unroll
    for (int o = 1; o < 32; o <<= 1) {
        float Ap = __shfl_up_sync(0xffffffffu, Ai, o);
        float Bp = __shfl_up_sync(0xffffffffu, Bi, o);
        if (lane >= o) { Bi = Bp * Ai + Bi; Ai = Ai * Ap; }
    }
    float sin = __shfl_up_sync(0xffffffffu, Bi, 1);
    if (lane == 0) sin = 0.f;
    float s = sin;
#pragma unroll
    for (int i = 0; i < 8; i++) {
        s = s * a[i] + bb[i];
        g_ys[idx0 + (size_t)i * DSV] = s;
    }
}

__global__ void yg_k(const float* __restrict__ Dp)
{
    int idx = blockIdx.x * blockDim.x + threadIdx.x;    // over TOKV*DIV/4
    if (idx >= TOKV * DIV / 4) return;
    int c4  = (idx % (DIV / 4)) * 4;
    int row = idx / (DIV / 4);
    float ys = g_ys[row * DSV + c4 / 96];
    float4 x1 = reinterpret_cast<const float4*>(g_x1)[idx];
    float4 dp = *reinterpret_cast<const float4*>(Dp + c4);
    float4 rs = *reinterpret_cast<const float4*>(
        g_xr + (size_t)row * (2 * DIV) + DIV + c4);
    float4 o;
    o.x = tf32r((ys + x1.x * dp.x) * (rs.x / (1.f + expf(-rs.x))));
    o.y = tf32r((ys + x1.y * dp.y) * (rs.y / (1.f + expf(-rs.y))));
    o.z = tf32r((ys + x1.z * dp.z) * (rs.z / (1.f + expf(-rs.z))));
    o.w = tf32r((ys + x1.w * dp.w) * (rs.w / (1.f + expf(-rs.w))));
    reinterpret_cast<float4*>(g_yg)[idx] = o;
}

// repack kan_coeff[j] (768,768,8) -> (768, 768*5) dense K-major, tf32-rounded
__global__ void repack_k(const float* __restrict__ coeff)
{
    int idx = blockIdx.x * blockDim.x + threadIdx.x;
    const int TOTAL = DIMV * KANK;
    if (idx >= TOTAL) return;
    int o = idx / KANK;
    int r2 = idx % KANK;
    int ii = r2 / GSV;
    int k = r2 % GSV;
    g_wkan[idx] = tf32r(coeff[((size_t)o * DIMV + ii) * 8 + k]);
}

// 4 h-values per thread -> 20 basis values = 5 aligned float4 stores
__global__ void basis_k()
{
    int idx = blockIdx.x * blockDim.x + threadIdx.x;    // over TOKV*DIMV/4
    if (idx >= TOKV * DIMV / 4) return;
    float4 h = reinterpret_cast<const float4*>(g_h)[idx];
    const float* hv = (const float*)&h;
    float outv[20];
    const float inv = 1.f / (0.4f + 1e-8f);
#pragma unroll
    for (int e = 0; e < 4; e++) {
        float xv = hv[e];
#pragma unroll
        for (int k = 0; k < GSV; k++) {
            float gk = -1.f + 0.4f * (float)k;
            float xs = (xv - gk) * inv;
            outv[e * GSV + k] = (xs >= 0.f && xs < 1.f) ? tf32r(xs) : 0.f;
        }
    }
    float4* dst = reinterpret_cast<float4*>(g_basis + (size_t)idx * 20);
#pragma unroll
    for (int q = 0; q < 5; q++)
        dst[q] = make_float4(outv[q * 4], outv[q * 4 + 1],
                             outv[q * 4 + 2], outv[q * 4 + 3]);
}

__global__ void resadd_k()
{
    int idx = blockIdx.x * blockDim.x + threadIdx.x;    // over TOKV*DIMV/4
    if (idx >= TOKV * DIMV / 4) return;
    float4 t = reinterpret_cast<const float4*>(g_tmp)[idx];
    float4 h = reinterpret_cast<const float4*>(g_h)[idx];
    h.x += t.x; h.y += t.y; h.z += t.z; h.w += t.w;
    reinterpret_cast<float4*>(g_h)[idx] = h;
    reinterpret_cast<float4*>(g_hr)[idx] = tf32r4(h);
}

__global__ void ln_k(const float* __restrict__ nw, const float* __restrict__ nb,
                     float* __restrict__ out)
{
    __shared__ float sh[DIMV];
    __shared__ float sbuf[8];
    int row = blockIdx.x;
    int tid = threadIdx.x;
    int lane = tid & 31, w = tid >> 5;

    float s = 0.f;
    for (int d = tid; d < DIMV; d += 256) {
        float v = g_h[(size_t)row * DIMV + d];
        sh[d] = v; s += v;
    }
#pragma unroll
    for (int o = 16; o; o >>= 1) s += __shfl_xor_sync(0xffffffffu, s, o);
    if (lane == 0) sbuf[w] = s;
    __syncthreads();
    if (w == 0) {
        float t = (lane < 8) ? sbuf[lane] : 0.f;
#pragma unroll
        for (int o = 4; o; o >>= 1) t += __shfl_xor_sync(0xffffffffu, t, o);
        if (lane == 0) sbuf[0] = t;
    }
    __syncthreads();
    float mu = sbuf[0] * (1.f / DIMV);
    __syncthreads();

    float s2 = 0.f;
    for (int d = tid; d < DIMV; d += 256) {
        float dv = sh[d] - mu;
        s2 += dv * dv;
    }
#pragma unroll
    for (int o = 16; o; o >>= 1) s2 += __shfl_xor_sync(0xffffffffu, s2, o);
    if (lane == 0) sbuf[w] = s2;
    __syncthreads();
    if (w == 0) {
        float t = (lane < 8) ? sbuf[lane] : 0.f;
#pragma unroll
        for (int o = 4; o; o >>= 1) t += __shfl_xor_sync(0xffffffffu, t, o);
        if (lane == 0) sbuf[0] = t;
    }
    __syncthreads();
    float var = sbuf[0] * (1.f / DIMV);
    float inv = rsqrtf(var + 1e-5f);
    for (int d = tid; d < DIMV; d += 256) {
        out[(size_t)row * DIMV + d] = (sh[d] - mu) * inv * nw[d] + nb[d];
    }
}

// ---------------- host orchestration ---------------------------------------

extern "C" void kernel_launch(void* const* d_in, const int* in_sizes, int n_in,
                              void* d_out, int out_size)
{
    const float* x       = (const float*)d_in[0];
    const float* patch_w = (const float*)d_in[1];
    const float* patch_b = (const float*)d_in[2];
    const float* pos     = (const float*)d_in[3];
    const float* in_w    = (const float*)d_in[4];
    const float* conv_w  = (const float*)d_in[5];
    const float* conv_b  = (const float*)d_in[6];
    const float* xpw     = (const float*)d_in[7];
    const float* dtw     = (const float*)d_in[8];
    const float* dtb     = (const float*)d_in[9];
    const float* alog    = (const float*)d_in[10];
    const float* Dp      = (const float*)d_in[11];
    const float* ow      = (const float*)d_in[12];
    const float* kbw     = (const float*)d_in[13];
    const float* kco     = (const float*)d_in[14];
    const float* kbi     = (const float*)d_in[15];
    const float* nw      = (const float*)d_in[16];
    const float* nb      = (const float*)d_in[17];
    float* out = (float*)d_out;

    cudaFuncSetAttribute(tgemm<false, false, false>, cudaFuncAttributeMaxDynamicSharedMemorySize, SMEMT);
    cudaFuncSetAttribute(tgemm<false, false, true >, cudaFuncAttributeMaxDynamicSharedMemorySize, SMEMT);
    cudaFuncSetAttribute(tgemm<true,  false, false>, cudaFuncAttributeMaxDynamicSharedMemorySize, SMEMT);
    cudaFuncSetAttribute(tgemm<false, true,  false>, cudaFuncAttributeMaxDynamicSharedMemorySize, SMEMT);

    float *p_tmp, *p_h, *p_hr, *p_xr, *p_x1, *p_yg, *p_basis, *p_wkan;
    float *p_wi, *p_wo, *p_wp, *p_wkb;
    cudaGetSymbolAddress((void**)&p_tmp,   g_tmp);
    cudaGetSymbolAddress((void**)&p_h,     g_h);
    cudaGetSymbolAddress((void**)&p_hr,    g_hr);
    cudaGetSymbolAddress((void**)&p_xr,    g_xr);
    cudaGetSymbolAddress((void**)&p_x1,    g_x1);
    cudaGetSymbolAddress((void**)&p_yg,    g_yg);
    cudaGetSymbolAddress((void**)&p_basis, g_basis);
    cudaGetSymbolAddress((void**)&p_wkan,  g_wkan);
    cudaGetSymbolAddress((void**)&p_wi,    g_wi);
    cudaGetSymbolAddress((void**)&p_wo,    g_wo);
    cudaGetSymbolAddress((void**)&p_wp,    g_wp);
    cudaGetSymbolAddress((void**)&p_wkb,   g_wkb);

    const int T = 256;
    const int MB = TOKV / 128;   // 64
    const int EW4 = (TOKV * DIMV / 4 + T - 1) / T;
    const int EX4 = (TOKV * DIV / 4 + T - 1) / T;

    // ---- weight tf32 rounding ----
    {
        int n4;
        n4 = NLV * 2 * DIV * DIMV / 4;
        round4_k<<<(n4 + T - 1) / T, T>>>(in_w, p_wi, n4);
        n4 = NLV * DIMV * DIV / 4;
        round4_k<<<(n4 + T - 1) / T, T>>>(ow, p_wo, n4);
        n4 = DIMV * DIMV / 4;
        round4_k<<<(n4 + T - 1) / T, T>>>(patch_w, p_wp, n4);
        n4 = 4 * DIMV * DIMV / 4;
        round4_k<<<(n4 + T - 1) / T, T>>>(kbw, p_wkb, n4);
    }

    // ---- patch embed ----
    im2col_k<<<EW4, T>>>(x);
    tgemm<true, false, false><<<dim3(DIMV / 128, MB), T, SMEMT>>>(
        p_tmp, p_wp, patch_b, p_h, nullptr, TOKV, DIMV, DIMV);
    addpos_k<<<EW4, T>>>(pos);

    for (int i = 0; i < NLV; i++) {
        tgemm<false, false, false><<<dim3(2 * DIV / 128, MB), T, SMEMT>>>(
            p_hr, p_wi + (size_t)i * 2 * DIV * DIMV, nullptr, p_xr, nullptr,
            TOKV, 2 * DIV, DIMV);
        conv_silu_k<<<EX4, T>>>(
            conv_w + (size_t)i * DIV * 4, conv_b + (size_t)i * DIV);
        dtbp_k<<<TOKV / 64, T>>>(
            dtw + (size_t)i * DSV * DIV, dtb + (size_t)i * DSV,
            xpw + (size_t)i * 2 * DSV * DIV, alog + (size_t)i * DSV);
        scan_k<<<64, 256>>>();
        yg_k<<<EX4, T>>>(Dp + (size_t)i * DIV);
        tgemm<false, false, true><<<dim3(DIMV / 128, MB), T, SMEMT>>>(
            p_yg, p_wo + (size_t)i * DIMV * DIV, nullptr, p_h, p_hr,
            TOKV, DIMV, DIV);

        if (i % 3 == 2) {
            int j = i / 3;
            repack_k<<<(DIMV * KANK + T - 1) / T, T>>>(
                kco + (size_t)j * DIMV * DIMV * 8);
            basis_k<<<EW4, T>>>();
            tgemm<true, false, false><<<dim3(DIMV / 128, MB), T, SMEMT>>>(
                p_hr, p_wkb + (size_t)j * DIMV * DIMV, kbi + (size_t)j * DIMV,
                p_tmp, nullptr, TOKV, DIMV, DIMV);
            tgemm<false, true, false><<<dim3(DIMV / 128, MB), T, SMEMT>>>(
                p_basis, p_wkan, nullptr, p_tmp, nullptr,
                TOKV, DIMV, KANK);
            resadd_k<<<EW4, T>>>();
        }
    }

    ln_k<<<TOKV, 256>>>(nw, nb, out);
}

// round 10
// speedup vs baseline: 1.0040x; 1.0040x over previous
#include <cuda_runtime.h>
#include <cuda_bf16.h>
#include <math.h>
#include <stdint.h>

#define DIMV 768
#define NLV 12
#define DSV 16
#define DIV 1536
#define TOKV 8192      // 32 batches * 256 tokens
#define LV 256
#define GSV 5
#define KANK (DIMV * GSV)   // 3840

// ---------------- scratch (static device globals; no allocation allowed) ----
__device__ float g_tmp[TOKV * DIMV];                 // im2col / KAN base accumulator
__device__ float g_h[TOKV * DIMV];                   // running hidden state (exact)
__device__ float g_hr[TOKV * DIMV];                  // tf32-rounded copy of h
__device__ float g_xr[(size_t)TOKV * 2 * DIV];       // in_proj output (x1|res)
__device__ float g_x1[(size_t)TOKV * DIV];           // post conv+silu
__device__ float g_yg[(size_t)TOKV * DIV];           // gated y (tf32-rounded)
__device__ float g_Ad[TOKV * DSV];
__device__ float g_Bd[TOKV * DSV];
__device__ float g_ys[TOKV * DSV];
__device__ float g_basis[(size_t)TOKV * KANK];       // KAN spline basis (rounded)
__device__ float g_wkan[(size_t)DIMV * KANK];        // repacked+rounded coeff
// tf32-rounded weight staging
__device__ float g_wi[(size_t)NLV * 2 * DIV * DIMV];
__device__ float g_wo[(size_t)NLV * DIMV * DIV];
__device__ float g_wp[DIMV * DIMV];
__device__ float g_wkb[4 * DIMV * DIMV];

// ---------------- PTX helpers ----------------------------------------------
__device__ __forceinline__ uint32_t smem_u32(const void* p) {
    uint32_t a;
    asm("{ .reg .u64 t; cvta.to.shared.u64 t, %1; cvt.u32.u64 %0, t; }"
        : "=r"(a) : "l"(p));
    return a;
}
__device__ __forceinline__ void ldsm4(uint32_t& r0, uint32_t& r1,
                                      uint32_t& r2, uint32_t& r3, uint32_t addr)
{
    asm volatile("ldmatrix.sync.aligned.m8n8.x4.shared.b16 {%0,%1,%2,%3}, [%4];"
                 : "=r"(r0), "=r"(r1), "=r"(r2), "=r"(r3) : "r"(addr));
}
__device__ __forceinline__ float tf32r(float v)
{
    uint32_t r;
    asm("cvt.rna.tf32.f32 %0, %1;" : "=r"(r) : "f"(v));
    return __uint_as_float(r);
}
__device__ __forceinline__ float4 tf32r4(float4 v)
{
    v.x = tf32r(v.x); v.y = tf32r(v.y); v.z = tf32r(v.z); v.w = tf32r(v.w);
    return v;
}
__device__ __forceinline__ void mma_tf32(float* c, const uint32_t* a, const uint32_t* b)
{
    asm volatile(
        "mma.sync.aligned.m16n8k8.row.col.f32.tf32.tf32.f32 "
        "{%0,%1,%2,%3}, {%4,%5,%6,%7}, {%8,%9}, {%0,%1,%2,%3};"
        : "+f"(c[0]), "+f"(c[1]), "+f"(c[2]), "+f"(c[3])
        : "r"(a[0]), "r"(a[1]), "r"(a[2]), "r"(a[3]), "r"(b[0]), "r"(b[1]));
}
__device__ __forceinline__ void cp16(uint32_t dst, const void* src)
{
    asm volatile("cp.async.cg.shared.global [%0], [%1], 16;"
                 :: "r"(dst), "l"(src) : "memory");
}
__device__ __forceinline__ void cp_commit()
{
    asm volatile("cp.async.commit_group;" ::: "memory");
}
template<int NN> __device__ __forceinline__ void cp_wait()
{
    asm volatile("cp.async.wait_group %0;" :: "n"(NN) : "memory");
}

// ---------------- tensor-core GEMM (TF32 mma.sync) --------------------------
// 128 threads, 4 warps in 2x2 grid, warp tile 64x64, CTA tile 128x128, BK=32,
// 2-stage cp.async double buffer. All operands pre-rounded to tf32-in-fp32.
// HADD: final = acc + C[] + H[]; write H and Cr=tf32(final); C untouched.
#define APITCH 144
#define TILE_B (128 * APITCH)        // 18432
#define STAGE_B (2 * TILE_B)         // 36864
#define SMEMT (2 * STAGE_B)          // 73728

template<bool BIAS, bool ACC, bool RST, bool HADD>
__global__ __launch_bounds__(128, 2)
void tgemm(const float* __restrict__ A, const float* __restrict__ W,
           const float* __restrict__ bias, float* __restrict__ C,
           float* __restrict__ Cr, float* __restrict__ H,
           int M, int N, int K)
{
    extern __shared__ char smem[];
    const uint32_t sb0 = smem_u32(smem);
    const int tid = threadIdx.x, lane = tid & 31, wid = tid >> 5;
    const int row0 = blockIdx.y * 128, col0 = blockIdx.x * 128;
    const int rm = (wid >> 1) * 64, cn = (wid & 1) * 64;

    const float* gA = A + (size_t)row0 * K;
    const float* gW = W + (size_t)col0 * K;

    const int lrow = tid >> 3;          // 0..15
    const int lch  = tid & 7;           // 16B chunk 0..7

    auto issue = [&](int p, int s) {
        const int k0 = p * 32;
        const uint32_t dstb = sb0 + s * STAGE_B;
#pragma unroll
        for (int i = 0; i < 8; i++) {
            int row = lrow + i * 16;
            cp16(dstb + row * APITCH + lch * 16,
                 gA + (size_t)row * K + k0 + lch * 4);
        }
#pragma unroll
        for (int i = 0; i < 8; i++) {
            int row = lrow + i * 16;
            cp16(dstb + TILE_B + row * APITCH + lch * 16,
                 gW + (size_t)row * K + k0 + lch * 4);
        }
        cp_commit();
    };

    float acc[4][8][4];
#pragma unroll
    for (int a = 0; a < 4; a++)
#pragma unroll
        for (int b = 0; b < 8; b++)
#pragma unroll
            for (int q = 0; q < 4; q++) acc[a][b][q] = 0.f;

    const uint32_t aOff = (uint32_t)(rm + ((lane >> 3) & 1) * 8 + (lane & 7)) * APITCH
                        + (lane >> 4) * 16;
    const uint32_t wOff = (uint32_t)(cn + ((lane >> 4) & 1) * 8 + (lane & 7)) * APITCH
                        + ((lane >> 3) & 1) * 16;

    const int npan = K >> 5;
    issue(0, 0);

    for (int p = 0; p < npan; p++) {
        const bool more = (p + 1 < npan);
        if (more) issue(p + 1, (p + 1) & 1);
        if (more) cp_wait<1>(); else cp_wait<0>();
        __syncthreads();

        const uint32_t sbase = sb0 + (p & 1) * STAGE_B;
#pragma unroll
        for (int ks = 0; ks < 4; ks++) {
            const uint32_t kb = ks * 32;
            uint32_t Af[4][4], Wf[8][2];
#pragma unroll
            for (int mt = 0; mt < 4; mt++)
                ldsm4(Af[mt][0], Af[mt][1], Af[mt][2], Af[mt][3],
                      sbase + aOff + mt * (16 * APITCH) + kb);
#pragma unroll
            for (int bt = 0; bt < 4; bt++) {
                uint32_t r0, r1, r2, r3;
                ldsm4(r0, r1, r2, r3,
                      sbase + TILE_B + wOff + bt * (16 * APITCH) + kb);
                Wf[bt * 2][0] = r0; Wf[bt * 2][1] = r1;
                Wf[bt * 2 + 1][0] = r2; Wf[bt * 2 + 1][1] = r3;
            }
#pragma unroll
            for (int mt = 0; mt < 4; mt++)
#pragma unroll
                for (int nt = 0; nt < 8; nt++)
                    mma_tf32(acc[mt][nt], Af[mt], Wf[nt]);
        }
        __syncthreads();
    }

    // epilogue
#pragma unroll
    for (int mt = 0; mt < 4; mt++) {
#pragma unroll
        for (int nt = 0; nt < 8; nt++) {
            int r = row0 + rm + mt * 16 + (lane >> 2);
            int c = col0 + cn + nt * 8 + (lane & 3) * 2;
            float bx = 0.f, by = 0.f;
            if (BIAS) { bx = bias[c]; by = bias[c + 1]; }
#pragma unroll
            for (int half = 0; half < 2; half++) {
                size_t off = (size_t)(r + half * 8) * N + c;
                float vx = acc[mt][nt][half * 2 + 0] + bx;
                float vy = acc[mt][nt][half * 2 + 1] + by;
                if (ACC) { vx += C[off]; vy += C[off + 1]; }
                if (HADD) {
                    vx += H[off]; vy += H[off + 1];
                    *reinterpret_cast<float2*>(H + off) = make_float2(vx, vy);
                    *reinterpret_cast<float2*>(Cr + off) =
                        make_float2(tf32r(vx), tf32r(vy));
                } else {
                    *reinterpret_cast<float2*>(C + off) = make_float2(vx, vy);
                    if (RST)
                        *reinterpret_cast<float2*>(Cr + off) =
                            make_float2(tf32r(vx), tf32r(vy));
                }
            }
        }
    }
}

// ---------------- elementwise / small kernels (float4-vectorized) ----------

__global__ void round4_k(const float* __restrict__ src, float* __restrict__ dst, int n4)
{
    int idx = blockIdx.x * blockDim.x + threadIdx.x;
    if (idx >= n4) return;
    reinterpret_cast<float4*>(dst)[idx] =
        tf32r4(reinterpret_cast<const float4*>(src)[idx]);
}

__global__ void im2col_k(const float* __restrict__ x)
{
    int idx = blockIdx.x * blockDim.x + threadIdx.x;    // over TOKV*DIMV/4
    if (idx >= TOKV * DIMV / 4) return;
    int col4 = (idx % (DIMV / 4)) * 4;
    int row  = idx / (DIMV / 4);
    int b = row >> 8, t = row & 255;
    int py = t >> 4, px = t & 15;
    int c = col4 >> 8, rj = col4 & 255;
    int r = rj >> 4, s = rj & 15;
    const float4 v = *reinterpret_cast<const float4*>(
        x + (((size_t)(b * 3 + c) * 256) + py * 16 + r) * 256 + px * 16 + s);
    reinterpret_cast<float4*>(g_tmp)[idx] = tf32r4(v);
}

__global__ void addpos_k(const float* __restrict__ pos)
{
    int idx = blockIdx.x * blockDim.x + threadIdx.x;    // over TOKV*DIMV/4
    if (idx >= TOKV * DIMV / 4) return;
    int d4  = idx % (DIMV / 4);
    int row = idx / (DIMV / 4);
    float4 h = reinterpret_cast<const float4*>(g_h)[idx];
    float4 p = reinterpret_cast<const float4*>(pos)[(row & 255) * (DIMV / 4) + d4];
    h.x += p.x; h.y += p.y; h.z += p.z; h.w += p.w;
    reinterpret_cast<float4*>(g_h)[idx] = h;
    reinterpret_cast<float4*>(g_hr)[idx] = tf32r4(h);
}

// depthwise causal conv (kernel 4) + silu, 4 channels / thread
__global__ void conv_silu_k(const float* __restrict__ cw, const float* __restrict__ cb)
{
    int idx = blockIdx.x * blockDim.x + threadIdx.x;    // over TOKV*DIV/4
    if (idx >= TOKV * DIV / 4) return;
    int c4  = (idx % (DIV / 4)) * 4;
    int row = idx / (DIV / 4);
    int l = row & 255;

    float4 a = *reinterpret_cast<const float4*>(cb + c4);
    float4 w0 = *reinterpret_cast<const float4*>(cw + (c4 + 0) * 4);
    float4 w1 = *reinterpret_cast<const float4*>(cw + (c4 + 1) * 4);
    float4 w2 = *reinterpret_cast<const float4*>(cw + (c4 + 2) * 4);
    float4 w3 = *reinterpret_cast<const float4*>(cw + (c4 + 3) * 4);
    const float* wk[4] = { (const float*)&w0, (const float*)&w1,
                           (const float*)&w2, (const float*)&w3 };
#pragma unroll
    for (int k = 0; k < 4; k++) {
        int l2 = l - 3 + k;
        if (l2 >= 0) {
            float4 xv = *reinterpret_cast<const float4*>(
                g_xr + (size_t)(row - 3 + k) * (2 * DIV) + c4);
            a.x = fmaf(xv.x, wk[0][k], a.x);
            a.y = fmaf(xv.y, wk[1][k], a.y);
            a.z = fmaf(xv.z, wk[2][k], a.z);
            a.w = fmaf(xv.w, wk[3][k], a.w);
        }
    }
    a.x = a.x / (1.f + expf(-a.x));
    a.y = a.y / (1.f + expf(-a.y));
    a.z = a.z / (1.f + expf(-a.z));
    a.w = a.w / (1.f + expf(-a.w));
    reinterpret_cast<float4*>(g_x1)[idx] = a;
}

// fused dt + Bp projection + softplus/Ad/Bd
__global__ __launch_bounds__(256)
void dtbp_k(const float* __restrict__ dtw, const float* __restrict__ dtb,
            const float* __restrict__ xpw, const float* __restrict__ alog)
{
    __shared__ float Xs[64][36];
    __shared__ float Ws2[32][33];

    const int tid = threadIdx.x;
    const int lane = tid & 31;
    const int wid = tid >> 5;
    const int row0 = blockIdx.x * 64;

    const int xrow = tid >> 3;
    const int xk4  = (tid & 7) * 4;

    float acc[8];
#pragma unroll
    for (int r = 0; r < 8; r++) acc[r] = 0.f;

    const float* wsrc = (xrow < 16)
        ? (dtw + (size_t)xrow * DIV)
        : (xpw + (size_t)xrow * DIV);

    for (int kt = 0; kt < DIV; kt += 32) {
        float4 xa = *(const float4*)(g_x1 + (size_t)(row0 + xrow) * DIV + kt + xk4);
        float4 xb = *(const float4*)(g_x1 + (size_t)(row0 + 32 + xrow) * DIV + kt + xk4);
        *(float4*)&Xs[xrow][xk4] = xa;
        *(float4*)&Xs[32 + xrow][xk4] = xb;
        float4 wv = *(const float4*)(wsrc + kt + xk4);
        Ws2[xrow][xk4 + 0] = wv.x; Ws2[xrow][xk4 + 1] = wv.y;
        Ws2[xrow][xk4 + 2] = wv.z; Ws2[xrow][xk4 + 3] = wv.w;
        __syncthreads();
#pragma unroll
        for (int kk = 0; kk < 32; kk++) {
            float w = Ws2[lane][kk];
#pragma unroll
            for (int r = 0; r < 8; r++)
                acc[r] = fmaf(Xs[wid * 8 + r][kk], w, acc[r]);
        }
        __syncthreads();
    }

    float dtb_v = (lane < DSV) ? dtb[lane] : 0.f;
    float negA  = (lane < DSV) ? -expf(alog[lane]) : 0.f;

#pragma unroll
    for (int r = 0; r < 8; r++) {
        int row = row0 + wid * 8 + r;
        const float* xr = g_x1 + (size_t)row * DIV;
        float s = xr[lane] + xr[lane + 32] + xr[lane + 64];
#pragma unroll
        for (int o = 16; o; o >>= 1) s += __shfl_xor_sync(0xffffffffu, s, o);
        float u = s * (1.f / 96.f);
        float bp = __shfl_sync(0xffffffffu, acc[r], (lane & 15) + 16);
        if (lane < DSV) {
            float raw = acc[r] + dtb_v;
            float dtv = fmaxf(raw, 0.f) + log1pf(expf(-fabsf(raw)));
            g_Ad[row * DSV + lane] = expf(negA * dtv);
            g_Bd[row * DSV + lane] = dtv * bp * u;
        }
    }
}

// warp-parallel linear-recurrence scan: one warp per (batch, state) pair.
__global__ void scan_k()   // <<<64, 256>>> : 512 warps
{
    int g = blockIdx.x * blockDim.x + threadIdx.x;
    int w = g >> 5, lane = g & 31;
    int b = w >> 4, n = w & 15;
    size_t idx0 = (size_t)b * LV * DSV + n + (size_t)(lane * 8) * DSV;

    float a[8], bb[8];
    float A = 1.f, B = 0.f;
#pragma unroll
    for (int i = 0; i < 8; i++) {
        a[i]  = g_Ad[idx0 + (size_t)i * DSV];
        bb[i] = g_Bd[idx0 + (size_t)i * DSV];
        B = B * a[i] + bb[i];
        A = A * a[i];
    }
    float Ai = A, Bi = B;
#pragma unroll
    for (int o = 1; o < 32; o <<= 1) {
        float Ap = __shfl_up_sync(0xffffffffu, Ai, o);
        float Bp = __shfl_up_sync(0xffffffffu, Bi, o);
        if (lane >= o) { Bi = Bp * Ai + Bi; Ai = Ai * Ap; }
    }
    float sin = __shfl_up_sync(0xffffffffu, Bi, 1);
    if (lane == 0) sin = 0.f;
    float s = sin;
#pragma unroll
    for (int i = 0; i < 8; i++) {
        s = s * a[i] + bb[i];
        g_ys[idx0 + (size_t)i * DSV] = s;
    }
}

__global__ void yg_k(const float* __restrict__ Dp)
{
    int idx = blockIdx.x * blockDim.x + threadIdx.x;    // over TOKV*DIV/4
    if (idx >= TOKV * DIV / 4) return;
    int c4  = (idx % (DIV / 4)) * 4;
    int row = idx / (DIV / 4);
    float ys = g_ys[row * DSV + c4 / 96];
    float4 x1 = reinterpret_cast<const float4*>(g_x1)[idx];
    float4 dp = *reinterpret_cast<const float4*>(Dp + c4);
    float4 rs = *reinterpret_cast<const float4*>(
        g_xr + (size_t)row * (2 * DIV) + DIV + c4);
    float4 o;
    o.x = tf32r((ys + x1.x * dp.x) * (rs.x / (1.f + expf(-rs.x))));
    o.y = tf32r((ys + x1.y * dp.y) * (rs.y / (1.f + expf(-rs.y))));
    o.z = tf32r((ys + x1.z * dp.z) * (rs.z / (1.f + expf(-rs.z))));
    o.w = tf32r((ys + x1.w * dp.w) * (rs.w / (1.f + expf(-rs.w))));
    reinterpret_cast<float4*>(g_yg)[idx] = o;
}

// repack kan_coeff[j] (768,768,8) -> (768, 768*5) dense K-major, tf32-rounded
__global__ void repack_k(const float* __restrict__ coeff)
{
    int idx = blockIdx.x * blockDim.x + threadIdx.x;
    const int TOTAL = DIMV * KANK;
    if (idx >= TOTAL) return;
    int o = idx / KANK;
    int r2 = idx % KANK;
    int ii = r2 / GSV;
    int k = r2 % GSV;
    g_wkan[idx] = tf32r(coeff[((size_t)o * DIMV + ii) * 8 + k]);
}

// 4 h-values per thread -> 20 basis values = 5 aligned float4 stores
__global__ void basis_k()
{
    int idx = blockIdx.x * blockDim.x + threadIdx.x;    // over TOKV*DIMV/4
    if (idx >= TOKV * DIMV / 4) return;
    float4 h = reinterpret_cast<const float4*>(g_h)[idx];
    const float* hv = (const float*)&h;
    float outv[20];
    const float inv = 1.f / (0.4f + 1e-8f);
#pragma unroll
    for (int e = 0; e < 4; e++) {
        float xv = hv[e];
#pragma unroll
        for (int k = 0; k < GSV; k++) {
            float gk = -1.f + 0.4f * (float)k;
            float xs = (xv - gk) * inv;
            outv[e * GSV + k] = (xs >= 0.f && xs < 1.f) ? tf32r(xs) : 0.f;
        }
    }
    float4* dst = reinterpret_cast<float4*>(g_basis + (size_t)idx * 20);
#pragma unroll
    for (int q = 0; q < 5; q++)
        dst[q] = make_float4(outv[q * 4], outv[q * 4 + 1],
                             outv[q * 4 + 2], outv[q * 4 + 3]);
}

__global__ void ln_k(const float* __restrict__ nw, const float* __restrict__ nb,
                     float* __restrict__ out)
{
    __shared__ float sh[DIMV];
    __shared__ float sbuf[8];
    int row = blockIdx.x;
    int tid = threadIdx.x;
    int lane = tid & 31, w = tid >> 5;

    float s = 0.f;
    for (int d = tid; d < DIMV; d += 256) {
        float v = g_h[(size_t)row * DIMV + d];
        sh[d] = v; s += v;
    }
#pragma unroll
    for (int o = 16; o; o >>= 1) s += __shfl_xor_sync(0xffffffffu, s, o);
    if (lane == 0) sbuf[w] = s;
    __syncthreads();
    if (w == 0) {
        float t = (lane < 8) ? sbuf[lane] : 0.f;
#pragma unroll
        for (int o = 4; o; o >>= 1) t += __shfl_xor_sync(0xffffffffu, t, o);
        if (lane == 0) sbuf[0] = t;
    }
    __syncthreads();
    float mu = sbuf[0] * (1.f / DIMV);
    __syncthreads();

    float s2 = 0.f;
    for (int d = tid; d < DIMV; d += 256) {
        float dv = sh[d] - mu;
        s2 += dv * dv;
    }
#pragma unroll
    for (int o = 16; o; o >>= 1) s2 += __shfl_xor_sync(0xffffffffu, s2, o);
    if (lane == 0) sbuf[w] = s2;
    __syncthreads();
    if (w == 0) {
        float t = (lane < 8) ? sbuf[lane] : 0.f;
#pragma unroll
        for (int o = 4; o; o >>= 1) t += __shfl_xor_sync(0xffffffffu, t, o);
        if (lane == 0) sbuf[0] = t;
    }
    __syncthreads();
    float var = sbuf[0] * (1.f / DIMV);
    float inv = rsqrtf(var + 1e-5f);
    for (int d = tid; d < DIMV; d += 256) {
        out[(size_t)row * DIMV + d] = (sh[d] - mu) * inv * nw[d] + nb[d];
    }
}

// ---------------- host orchestration ---------------------------------------

extern "C" void kernel_launch(void* const* d_in, const int* in_sizes, int n_in,
                              void* d_out, int out_size)
{
    const float* x       = (const float*)d_in[0];
    const float* patch_w = (const float*)d_in[1];
    const float* patch_b = (const float*)d_in[2];
    const float* pos     = (const float*)d_in[3];
    const float* in_w    = (const float*)d_in[4];
    const float* conv_w  = (const float*)d_in[5];
    const float* conv_b  = (const float*)d_in[6];
    const float* xpw     = (const float*)d_in[7];
    const float* dtw     = (const float*)d_in[8];
    const float* dtb     = (const float*)d_in[9];
    const float* alog    = (const float*)d_in[10];
    const float* Dp      = (const float*)d_in[11];
    const float* ow      = (const float*)d_in[12];
    const float* kbw     = (const float*)d_in[13];
    const float* kco     = (const float*)d_in[14];
    const float* kbi     = (const float*)d_in[15];
    const float* nw      = (const float*)d_in[16];
    const float* nb      = (const float*)d_in[17];
    float* out = (float*)d_out;

    cudaFuncSetAttribute(tgemm<false, false, false, false>, cudaFuncAttributeMaxDynamicSharedMemorySize, SMEMT);
    cudaFuncSetAttribute(tgemm<false, false, true,  false>, cudaFuncAttributeMaxDynamicSharedMemorySize, SMEMT);
    cudaFuncSetAttribute(tgemm<true,  false, false, false>, cudaFuncAttributeMaxDynamicSharedMemorySize, SMEMT);
    cudaFuncSetAttribute(tgemm<false, true,  false, true >, cudaFuncAttributeMaxDynamicSharedMemorySize, SMEMT);

    float *p_tmp, *p_h, *p_hr, *p_xr, *p_x1, *p_yg, *p_basis, *p_wkan;
    float *p_wi, *p_wo, *p_wp, *p_wkb;
    cudaGetSymbolAddress((void**)&p_tmp,   g_tmp);
    cudaGetSymbolAddress((void**)&p_h,     g_h);
    cudaGetSymbolAddress((void**)&p_hr,    g_hr);
    cudaGetSymbolAddress((void**)&p_xr,    g_xr);
    cudaGetSymbolAddress((void**)&p_x1,    g_x1);
    cudaGetSymbolAddress((void**)&p_yg,    g_yg);
    cudaGetSymbolAddress((void**)&p_basis, g_basis);
    cudaGetSymbolAddress((void**)&p_wkan,  g_wkan);
    cudaGetSymbolAddress((void**)&p_wi,    g_wi);
    cudaGetSymbolAddress((void**)&p_wo,    g_wo);
    cudaGetSymbolAddress((void**)&p_wp,    g_wp);
    cudaGetSymbolAddress((void**)&p_wkb,   g_wkb);

    const int T = 256;
    const int GT = 128;          // tgemm threads
    const int MB = TOKV / 128;   // 64
    const int EW4 = (TOKV * DIMV / 4 + T - 1) / T;
    const int EX4 = (TOKV * DIV / 4 + T - 1) / T;

    // ---- weight tf32 rounding ----
    {
        int n4;
        n4 = NLV * 2 * DIV * DIMV / 4;
        round4_k<<<(n4 + T - 1) / T, T>>>(in_w, p_wi, n4);
        n4 = NLV * DIMV * DIV / 4;
        round4_k<<<(n4 + T - 1) / T, T>>>(ow, p_wo, n4);
        n4 = DIMV * DIMV / 4;
        round4_k<<<(n4 + T - 1) / T, T>>>(patch_w, p_wp, n4);
        n4 = 4 * DIMV * DIMV / 4;
        round4_k<<<(n4 + T - 1) / T, T>>>(kbw, p_wkb, n4);
    }

    // ---- patch embed ----
    im2col_k<<<EW4, T>>>(x);
    tgemm<true, false, false, false><<<dim3(DIMV / 128, MB), GT, SMEMT>>>(
        p_tmp, p_wp, patch_b, p_h, nullptr, nullptr, TOKV, DIMV, DIMV);
    addpos_k<<<EW4, T>>>(pos);

    for (int i = 0; i < NLV; i++) {
        tgemm<false, false, false, false><<<dim3(2 * DIV / 128, MB), GT, SMEMT>>>(
            p_hr, p_wi + (size_t)i * 2 * DIV * DIMV, nullptr, p_xr, nullptr, nullptr,
            TOKV, 2 * DIV, DIMV);
        conv_silu_k<<<EX4, T>>>(
            conv_w + (size_t)i * DIV * 4, conv_b + (size_t)i * DIV);
        dtbp_k<<<TOKV / 64, T>>>(
            dtw + (size_t)i * DSV * DIV, dtb + (size_t)i * DSV,
            xpw + (size_t)i * 2 * DSV * DIV, alog + (size_t)i * DSV);
        scan_k<<<64, 256>>>();
        yg_k<<<EX4, T>>>(Dp + (size_t)i * DIV);
        tgemm<false, false, true, false><<<dim3(DIMV / 128, MB), GT, SMEMT>>>(
            p_yg, p_wo + (size_t)i * DIMV * DIV, nullptr, p_h, p_hr, nullptr,
            TOKV, DIMV, DIV);

        if (i % 3 == 2) {
            int j = i / 3;
            repack_k<<<(DIMV * KANK + T - 1) / T, T>>>(
                kco + (size_t)j * DIMV * DIMV * 8);
            basis_k<<<EW4, T>>>();
            tgemm<true, false, false, false><<<dim3(DIMV / 128, MB), GT, SMEMT>>>(
                p_hr, p_wkb + (size_t)j * DIMV * DIMV, kbi + (size_t)j * DIMV,
                p_tmp, nullptr, nullptr, TOKV, DIMV, DIMV);
            // spline GEMM + fused residual add: h = spline + tmp(base) + h
            tgemm<false, true, false, true><<<dim3(DIMV / 128, MB), GT, SMEMT>>>(
                p_basis, p_wkan, nullptr, p_tmp, p_hr, p_h,
                TOKV, DIMV, KANK);
        }
    }

    ln_k<<<TOKV, 256>>>(nw, nb, out);
}